// round 1
// baseline (speedup 1.0000x reference)
#include <cuda_runtime.h>
#include <math.h>

#define BATCH 32
#define SEQT  512
#define HID   512
#define G4    2048   // 4*HID

// out tensor layout in d_out (fp32):
//   out   [B][T][2H]   : 32*512*1024 = 16,777,216 floats at offset 0
//   h_n   [2][B][H]    : 32,768 floats at offset 16,777,216
//   c_n   [2][B][H]    : 32,768 floats at offset 16,809,984
#define OUT_HN 16777216
#define OUT_CN 16809984

// Scratch (device globals; allocation-free rule compliant)
__device__ float g_gx[2][SEQT][BATCH][G4];      // precomputed x@W_ih^T + b_ih + b_hh
__device__ float g_hbuf[2][2][BATCH][HID];      // ping-pong hidden state per dir
__device__ float g_c[2][BATCH][HID];            // cell state per dir

// ---------------------------------------------------------------------------
// Init: load h0/c0 into state buffers
// ---------------------------------------------------------------------------
__global__ void init_state_kernel(const float* __restrict__ h0,
                                  const float* __restrict__ c0) {
    int idx = blockIdx.x * blockDim.x + threadIdx.x;   // 0..32767
    int dir = idx / (BATCH * HID);
    int rem = idx % (BATCH * HID);
    int b = rem / HID, j = rem % HID;
    g_hbuf[0][dir][b][j] = h0[idx];
    g_c[dir][b][j]       = c0[idx];
}

// ---------------------------------------------------------------------------
// Phase 1: gx[dir][t][b][g] = sum_i x[b][tt][i]*w_ih[dir][g][i] + bi[g] + bh[g]
// where tt = t (fwd) or T-1-t (rev). Tiled fp32 SGEMM: BM=BN=64, BK=16,
// 256 threads, 4x4 microtile.
// ---------------------------------------------------------------------------
#define BM 64
#define BN 64
#define BK 16

__global__ void gemm_ih_kernel(const float* __restrict__ x,
                               const float* __restrict__ w_f,
                               const float* __restrict__ w_r,
                               const float* __restrict__ bi_f,
                               const float* __restrict__ bh_f,
                               const float* __restrict__ bi_r,
                               const float* __restrict__ bh_r) {
    const int dir = blockIdx.z;
    const float* __restrict__ w  = dir ? w_r  : w_f;
    const float* __restrict__ bi = dir ? bi_r : bi_f;
    const float* __restrict__ bh = dir ? bh_r : bh_f;

    const int rm0 = blockIdx.y * BM;   // row tile over T*B = 16384 (row = t*32+b)
    const int cn0 = blockIdx.x * BN;   // col tile over 4H = 2048

    __shared__ float As[BK][BM + 4];
    __shared__ float Ws[BK][BN + 4];

    const int tid = threadIdx.x;           // 256
    const int tr = tid / 16;               // 0..15 : output row group
    const int tc = tid % 16;               // 0..15 : output col group

    // loaders: each thread one float4 of A and one of W per K-chunk
    const int l_row = tid >> 2;            // 0..63
    const int l_k4  = (tid & 3) << 2;      // 0,4,8,12

    const int r  = rm0 + l_row;
    int       tt = r >> 5;                 // t = r/32
    const int bb = r & 31;                 // b = r%32
    if (dir) tt = (SEQT - 1) - tt;
    const float* a_ptr = x + ((size_t)bb * SEQT + tt) * HID;
    const float* w_ptr = w + (size_t)(cn0 + l_row) * HID;

    float acc[4][4];
#pragma unroll
    for (int i = 0; i < 4; i++)
#pragma unroll
        for (int j = 0; j < 4; j++) acc[i][j] = 0.0f;

    for (int k0 = 0; k0 < HID; k0 += BK) {
        float4 av = *(const float4*)(a_ptr + k0 + l_k4);
        float4 wv = *(const float4*)(w_ptr + k0 + l_k4);
        __syncthreads();
        As[l_k4 + 0][l_row] = av.x;
        As[l_k4 + 1][l_row] = av.y;
        As[l_k4 + 2][l_row] = av.z;
        As[l_k4 + 3][l_row] = av.w;
        Ws[l_k4 + 0][l_row] = wv.x;
        Ws[l_k4 + 1][l_row] = wv.y;
        Ws[l_k4 + 2][l_row] = wv.z;
        Ws[l_k4 + 3][l_row] = wv.w;
        __syncthreads();
#pragma unroll
        for (int kk = 0; kk < BK; kk++) {
            float4 a4 = *(const float4*)&As[kk][tr * 4];
            float4 w4 = *(const float4*)&Ws[kk][tc * 4];
            acc[0][0] += a4.x * w4.x; acc[0][1] += a4.x * w4.y;
            acc[0][2] += a4.x * w4.z; acc[0][3] += a4.x * w4.w;
            acc[1][0] += a4.y * w4.x; acc[1][1] += a4.y * w4.y;
            acc[1][2] += a4.y * w4.z; acc[1][3] += a4.y * w4.w;
            acc[2][0] += a4.z * w4.x; acc[2][1] += a4.z * w4.y;
            acc[2][2] += a4.z * w4.z; acc[2][3] += a4.z * w4.w;
            acc[3][0] += a4.w * w4.x; acc[3][1] += a4.w * w4.y;
            acc[3][2] += a4.w * w4.z; acc[3][3] += a4.w * w4.w;
        }
    }

    float* gxp = &g_gx[dir][0][0][0];
    const int cc = cn0 + tc * 4;
    const float bsum0 = bi[cc + 0] + bh[cc + 0];
    const float bsum1 = bi[cc + 1] + bh[cc + 1];
    const float bsum2 = bi[cc + 2] + bh[cc + 2];
    const float bsum3 = bi[cc + 3] + bh[cc + 3];
#pragma unroll
    for (int i = 0; i < 4; i++) {
        const int rr = rm0 + tr * 4 + i;   // == t*32 + b, matches gx row layout
        float4 o;
        o.x = acc[i][0] + bsum0;
        o.y = acc[i][1] + bsum1;
        o.z = acc[i][2] + bsum2;
        o.w = acc[i][3] + bsum3;
        *(float4*)(gxp + (size_t)rr * G4 + cc) = o;
    }
}

// ---------------------------------------------------------------------------
// Phase 2: one step of the recurrence, both directions.
// Grid: (HID/JT=32, 2 dirs), 256 threads.
// Each block owns hidden units [j0, j0+16) for all 32 batches:
//   computes the 64 gate columns {gg*512 + j0 + u : gg in 0..3, u in 0..15}
//   of  h @ W_hh^T, adds gx, applies gate nonlinearities, updates c/h,
//   writes output slice (and h_n/c_n at the last step).
// ---------------------------------------------------------------------------
#define JT 16

__device__ __forceinline__ float sigf(float xv) {
    return 1.0f / (1.0f + expf(-xv));
}

__global__ void lstm_step_kernel(const float* __restrict__ w_hh_f,
                                 const float* __restrict__ w_hh_r,
                                 float* __restrict__ out, int t) {
    const int dir = blockIdx.y;
    const int j0  = blockIdx.x * JT;
    const float* __restrict__ w   = dir ? w_hh_r : w_hh_f;
    const float* __restrict__ hin = &g_hbuf[t & 1][dir][0][0];
    float* __restrict__ hout      = &g_hbuf[(t & 1) ^ 1][dir][0][0];

    __shared__ float Hs[16][36];       // [kk][b], padded (144B rows: 16B aligned)
    __shared__ float Ws[16][66];       // [kk][c], padded (264B rows: 8B aligned)
    __shared__ float P[BATCH][80];     // gate preactivations, c = gg*16+u

    const int tid = threadIdx.x;       // 256
    const int tr  = tid >> 5;          // 0..7  : batch group (4 batches)
    const int tc  = tid & 31;          // 0..31 : gate-col group (2 cols)

    // loader indices (one float4 per thread per chunk)
    const int wc   = tid >> 2;                          // 0..63 gate col
    const int wk4  = (tid & 3) << 2;                    // 0,4,8,12
    const int wrow = (wc >> 4) * HID + j0 + (wc & 15);  // w_hh row for col wc
    const float* wp = w + (size_t)wrow * HID + wk4;
    const float* hp = hin + (tid >> 2) * HID + wk4;     // valid for tid < 128

    float acc[4][2];
#pragma unroll
    for (int i = 0; i < 4; i++) { acc[i][0] = 0.0f; acc[i][1] = 0.0f; }

    for (int k0 = 0; k0 < HID; k0 += 16) {
        float4 wv = *(const float4*)(wp + k0);
        float4 hv = make_float4(0.f, 0.f, 0.f, 0.f);
        if (tid < 128) hv = *(const float4*)(hp + k0);
        __syncthreads();
        Ws[wk4 + 0][wc] = wv.x;
        Ws[wk4 + 1][wc] = wv.y;
        Ws[wk4 + 2][wc] = wv.z;
        Ws[wk4 + 3][wc] = wv.w;
        if (tid < 128) {
            const int hb = tid >> 2;   // 0..31
            Hs[wk4 + 0][hb] = hv.x;
            Hs[wk4 + 1][hb] = hv.y;
            Hs[wk4 + 2][hb] = hv.z;
            Hs[wk4 + 3][hb] = hv.w;
        }
        __syncthreads();
#pragma unroll
        for (int kk = 0; kk < 16; kk++) {
            float4 h4 = *(const float4*)&Hs[kk][tr * 4];
            float2 w2 = *(const float2*)&Ws[kk][tc * 2];
            acc[0][0] += h4.x * w2.x; acc[0][1] += h4.x * w2.y;
            acc[1][0] += h4.y * w2.x; acc[1][1] += h4.y * w2.y;
            acc[2][0] += h4.z * w2.x; acc[2][1] += h4.z * w2.y;
            acc[3][0] += h4.w * w2.x; acc[3][1] += h4.w * w2.y;
        }
    }

    // write preactivations (GEMM part + precomputed gx incl. biases)
    const float* gxp = &g_gx[dir][t][0][0];
#pragma unroll
    for (int i = 0; i < 4; i++) {
        const int b = tr * 4 + i;
#pragma unroll
        for (int j = 0; j < 2; j++) {
            const int c = tc * 2 + j;
            const int gidx = (c >> 4) * HID + j0 + (c & 15);
            P[b][c] = acc[i][j] + gxp[(size_t)b * G4 + gidx];
        }
    }
    __syncthreads();

    // pointwise: 32 batches x 16 units = 512 items, 2 per thread
    const int tout = dir ? (SEQT - 1 - t) : t;
#pragma unroll
    for (int rep = 0; rep < 2; rep++) {
        const int idx = rep * 256 + tid;
        const int b = idx >> 4;
        const int u = idx & 15;
        const int j = j0 + u;
        const float iv = sigf(P[b][u]);
        const float fv = sigf(P[b][16 + u]);
        const float gv = tanhf(P[b][32 + u]);
        const float ov = sigf(P[b][48 + u]);
        const float cold = g_c[dir][b][j];
        const float cnew = fv * cold + iv * gv;
        const float hnew = ov * tanhf(cnew);
        g_c[dir][b][j] = cnew;
        hout[b * HID + j] = hnew;
        out[((size_t)b * SEQT + tout) * (2 * HID) + dir * HID + j] = hnew;
        if (t == SEQT - 1) {
            out[OUT_HN + ((size_t)dir * BATCH + b) * HID + j] = hnew;
            out[OUT_CN + ((size_t)dir * BATCH + b) * HID + j] = cnew;
        }
    }
}

// ---------------------------------------------------------------------------
// Launch
// ---------------------------------------------------------------------------
extern "C" void kernel_launch(void* const* d_in, const int* in_sizes, int n_in,
                              void* d_out, int out_size) {
    const float* x      = (const float*)d_in[0];
    const float* h0     = (const float*)d_in[1];
    const float* c0     = (const float*)d_in[2];
    const float* w_ih_f = (const float*)d_in[3];
    const float* w_hh_f = (const float*)d_in[4];
    const float* b_ih_f = (const float*)d_in[5];
    const float* b_hh_f = (const float*)d_in[6];
    const float* w_ih_r = (const float*)d_in[7];
    const float* w_hh_r = (const float*)d_in[8];
    const float* b_ih_r = (const float*)d_in[9];
    const float* b_hh_r = (const float*)d_in[10];
    float* out = (float*)d_out;

    init_state_kernel<<<128, 256>>>(h0, c0);

    dim3 ggrid(G4 / BN, (SEQT * BATCH) / BM, 2);   // (32, 256, 2)
    gemm_ih_kernel<<<ggrid, 256>>>(x, w_ih_f, w_ih_r,
                                   b_ih_f, b_hh_f, b_ih_r, b_hh_r);

    dim3 sgrid(HID / JT, 2);                       // (32, 2)
    for (int t = 0; t < SEQT; t++) {
        lstm_step_kernel<<<sgrid, 256>>>(w_hh_f, w_hh_r, out, t);
    }
}

// round 2
// speedup vs baseline: 1.7964x; 1.7964x over previous
#include <cuda_runtime.h>
#include <math.h>

#define BATCH 32
#define SEQT  512
#define HID   512
#define G4    2048   // 4*HID

// out layout (fp32): out[B][T][2H] @0, h_n[2][B][H] @16777216, c_n @16809984
#define OUT_HN 16777216
#define OUT_CN 16809984

// ---------------------------------------------------------------------------
// Device globals (allocation-free scratch)
// ---------------------------------------------------------------------------
__device__ float g_gx[2][SEQT][BATCH][G4];       // x@W_ih^T + b_ih + b_hh
__device__ float g_hT[2][2][HID][BATCH];         // [parity][dir][unit][batch]
__device__ int   g_arrive[2];                    // per-dir step arrival counters

// ---------------------------------------------------------------------------
// Packed fp32x2 FMA (Blackwell FFMA2; only reachable via PTX)
// ---------------------------------------------------------------------------
__device__ __forceinline__ float2 f2fma(float2 a, float2 b, float2 c) {
    unsigned long long ra = *reinterpret_cast<unsigned long long*>(&a);
    unsigned long long rb = *reinterpret_cast<unsigned long long*>(&b);
    unsigned long long rc = *reinterpret_cast<unsigned long long*>(&c);
    unsigned long long rd;
    asm("fma.rn.f32x2 %0, %1, %2, %3;" : "=l"(rd) : "l"(ra), "l"(rb), "l"(rc));
    return *reinterpret_cast<float2*>(&rd);
}

__device__ __forceinline__ float sigf(float x) { return 1.0f / (1.0f + __expf(-x)); }
__device__ __forceinline__ float tanhx(float x) { return 2.0f / (1.0f + __expf(-2.0f * x)) - 1.0f; }

// ---------------------------------------------------------------------------
// Init: h0 -> hT[0], reset arrival counters
// ---------------------------------------------------------------------------
__global__ void init_state_kernel(const float* __restrict__ h0) {
    int idx = blockIdx.x * blockDim.x + threadIdx.x;   // 0..32767
    int dir = idx >> 14;
    int rem = idx & 16383;
    int b = rem >> 9, j = rem & 511;
    g_hT[0][dir][j][b] = h0[idx];
    if (idx == 0) { g_arrive[0] = 0; g_arrive[1] = 0; }
}

// ---------------------------------------------------------------------------
// Phase 1: gx = x @ W_ih^T + biases, both dirs (rev dir time-reversed).
// BM=BN=64, BK=16, 256 threads, 4x4 microtile, packed f32x2 (A dup'd).
// ---------------------------------------------------------------------------
#define BM 64
#define BN 64
#define BK 16

__global__ __launch_bounds__(256) void gemm_ih_kernel(
        const float* __restrict__ x,
        const float* __restrict__ w_f, const float* __restrict__ w_r,
        const float* __restrict__ bi_f, const float* __restrict__ bh_f,
        const float* __restrict__ bi_r, const float* __restrict__ bh_r) {
    const int dir = blockIdx.z;
    const float* __restrict__ w  = dir ? w_r  : w_f;
    const float* __restrict__ bi = dir ? bi_r : bi_f;
    const float* __restrict__ bh = dir ? bh_r : bh_f;

    const int rm0 = blockIdx.y * BM;   // rows over T*B (row = t*32+b)
    const int cn0 = blockIdx.x * BN;   // cols over 4H

    __shared__ __align__(16) float2 Asd[BK][BM + 2];   // A rows, duplicated lanes
    __shared__ __align__(16) float  Ws[BK][BN + 4];

    const int tid = threadIdx.x;
    const int tr = tid / 16;           // 0..15 row group
    const int tc = tid % 16;           // 0..15 col group

    const int l_row = tid >> 2;        // 0..63
    const int l_k4  = (tid & 3) << 2;  // 0,4,8,12

    const int r  = rm0 + l_row;
    int       tt = r >> 5;
    const int bb = r & 31;
    if (dir) tt = (SEQT - 1) - tt;
    const float* a_ptr = x + ((size_t)bb * SEQT + tt) * HID;
    const float* w_ptr = w + (size_t)(cn0 + l_row) * HID;

    float2 acc[4][2];
#pragma unroll
    for (int i = 0; i < 4; i++) { acc[i][0] = make_float2(0.f, 0.f); acc[i][1] = make_float2(0.f, 0.f); }

    for (int k0 = 0; k0 < HID; k0 += BK) {
        float4 av = *(const float4*)(a_ptr + k0 + l_k4);
        float4 wv = *(const float4*)(w_ptr + k0 + l_k4);
        __syncthreads();
        Asd[l_k4 + 0][l_row] = make_float2(av.x, av.x);
        Asd[l_k4 + 1][l_row] = make_float2(av.y, av.y);
        Asd[l_k4 + 2][l_row] = make_float2(av.z, av.z);
        Asd[l_k4 + 3][l_row] = make_float2(av.w, av.w);
        Ws[l_k4 + 0][l_row] = wv.x;
        Ws[l_k4 + 1][l_row] = wv.y;
        Ws[l_k4 + 2][l_row] = wv.z;
        Ws[l_k4 + 3][l_row] = wv.w;
        __syncthreads();
#pragma unroll
        for (int kk = 0; kk < BK; kk++) {
            float4 ad0 = *(const float4*)&Asd[kk][tr * 4];       // rows r0,r1 dup
            float4 ad1 = *(const float4*)&Asd[kk][tr * 4 + 2];   // rows r2,r3 dup
            float4 w4  = *(const float4*)&Ws[kk][tc * 4];
            float2 w01 = make_float2(w4.x, w4.y);
            float2 w23 = make_float2(w4.z, w4.w);
            float2 a0 = make_float2(ad0.x, ad0.y);
            float2 a1 = make_float2(ad0.z, ad0.w);
            float2 a2 = make_float2(ad1.x, ad1.y);
            float2 a3 = make_float2(ad1.z, ad1.w);
            acc[0][0] = f2fma(a0, w01, acc[0][0]); acc[0][1] = f2fma(a0, w23, acc[0][1]);
            acc[1][0] = f2fma(a1, w01, acc[1][0]); acc[1][1] = f2fma(a1, w23, acc[1][1]);
            acc[2][0] = f2fma(a2, w01, acc[2][0]); acc[2][1] = f2fma(a2, w23, acc[2][1]);
            acc[3][0] = f2fma(a3, w01, acc[3][0]); acc[3][1] = f2fma(a3, w23, acc[3][1]);
        }
    }

    float* gxp = &g_gx[dir][0][0][0];
    const int cc = cn0 + tc * 4;
    const float bsum0 = bi[cc + 0] + bh[cc + 0];
    const float bsum1 = bi[cc + 1] + bh[cc + 1];
    const float bsum2 = bi[cc + 2] + bh[cc + 2];
    const float bsum3 = bi[cc + 3] + bh[cc + 3];
#pragma unroll
    for (int i = 0; i < 4; i++) {
        const int rr = rm0 + tr * 4 + i;
        float4 o;
        o.x = acc[i][0].x + bsum0;
        o.y = acc[i][0].y + bsum1;
        o.z = acc[i][1].x + bsum2;
        o.w = acc[i][1].y + bsum3;
        *(float4*)(gxp + (size_t)rr * G4 + cc) = o;
    }
}

// ---------------------------------------------------------------------------
// Phase 2: persistent recurrence. 128 blocks (64/dir), 128 threads each.
// Block owns 8 hidden units (32 gate cols). W slice lives dup'd in shared
// for all 512 steps. Per-dir spin sync via global counter.
// ---------------------------------------------------------------------------
#define NBLK_PER_DIR 64
#define JB 8
#define NC 32

#define SM_WD 0                    // float2 Wd[512][32] = 131072 B
#define SM_HS 131072               // float  Hs[512][32] =  65536 B
#define SM_P  196608               // float  P[32][34]   =   4352 B
#define SMEM_TOTAL (196608 + 4352)

__global__ __launch_bounds__(128, 1)
void lstm_persistent_kernel(const float* __restrict__ w_hh_f,
                            const float* __restrict__ w_hh_r,
                            const float* __restrict__ c0,
                            float* __restrict__ out) {
    extern __shared__ char smem_raw[];
    float2* Wd = (float2*)(smem_raw + SM_WD);
    float*  Hs = (float*)(smem_raw + SM_HS);
    float*  P  = (float*)(smem_raw + SM_P);    // row stride 34

    const int tid = threadIdx.x;
    const int dir = blockIdx.x >> 6;
    const int blk = blockIdx.x & 63;
    const int j0  = blk * JB;
    const float* __restrict__ w = dir ? w_hh_r : w_hh_f;

    // ---- load + duplicate W slice (once) ----
    {
        const int c  = tid >> 2;                 // 0..31 local gate col
        const int kq = (tid & 3) * 4;
        const int g = c >> 3, u = c & 7;
        const float* wrow = w + (size_t)(g * HID + j0 + u) * HID;
        for (int k0 = 0; k0 < HID; k0 += 16) {
            float4 v = *(const float4*)(wrow + k0 + kq);
            Wd[(k0 + kq + 0) * NC + c] = make_float2(v.x, v.x);
            Wd[(k0 + kq + 1) * NC + c] = make_float2(v.y, v.y);
            Wd[(k0 + kq + 2) * NC + c] = make_float2(v.z, v.z);
            Wd[(k0 + kq + 3) * NC + c] = make_float2(v.w, v.w);
        }
    }

    // ---- cell state in registers: this thread owns (pu,pb) and (pu+4,pb) ----
    const int pu = tid >> 5;                     // 0..3
    const int pb = tid & 31;
    float creg0 = c0[((size_t)dir * BATCH + pb) * HID + j0 + pu];
    float creg1 = c0[((size_t)dir * BATCH + pb) * HID + j0 + pu + 4];

    // ---- GEMM thread coords: 8 batch-groups x 16 col-groups ----
    const int bg  = tid & 7;
    const int cg  = tid >> 3;
    const int b0  = bg * 4;
    const int cl0 = cg * 2;
    const int gcol0 = ((cl0)     >> 3) * HID + j0 + ((cl0)     & 7);
    const int gcol1 = ((cl0 + 1) >> 3) * HID + j0 + ((cl0 + 1) & 7);

    const float4* hT4b0 = (const float4*)&g_hT[0][dir][0][0];
    const float4* hT4b1 = (const float4*)&g_hT[1][dir][0][0];
    float4* Hs4 = (float4*)Hs;
    int* arrive = &g_arrive[dir];

    __syncthreads();

    for (int t = 0; t < SEQT; t++) {
        // prefetch gx (independent of h)
        const float* gxp = &g_gx[dir][t][0][0];
        float gx00 = gxp[(b0 + 0) * G4 + gcol0], gx01 = gxp[(b0 + 0) * G4 + gcol1];
        float gx10 = gxp[(b0 + 1) * G4 + gcol0], gx11 = gxp[(b0 + 1) * G4 + gcol1];
        float gx20 = gxp[(b0 + 2) * G4 + gcol0], gx21 = gxp[(b0 + 2) * G4 + gcol1];
        float gx30 = gxp[(b0 + 3) * G4 + gcol0], gx31 = gxp[(b0 + 3) * G4 + gcol1];

        // wait for all same-dir blocks to finish step t-1
        if (t > 0 && tid == 0) {
            const int target = NBLK_PER_DIR * t;
            int v;
            do {
                asm volatile("ld.acquire.gpu.s32 %0, [%1];" : "=r"(v) : "l"(arrive));
            } while (v < target);
        }
        __syncthreads();

        // stage h (64KB) into shared, coalesced
        const float4* src = (t & 1) ? hT4b1 : hT4b0;
#pragma unroll 8
        for (int it = 0; it < 32; it++) Hs4[it * 128 + tid] = src[it * 128 + tid];
        __syncthreads();

        // GEMM: C[b][c] = sum_k h[b][k] * Whh[c][k], lanes = batch pairs
        float2 a00 = make_float2(0.f, 0.f), a01 = make_float2(0.f, 0.f);
        float2 a10 = make_float2(0.f, 0.f), a11 = make_float2(0.f, 0.f);
#pragma unroll 16
        for (int k = 0; k < HID; k++) {
            float4 h4 = *(const float4*)&Hs[k * NC + b0];
            float4 wv = *(const float4*)&Wd[k * NC + cl0];
            float2 h01 = make_float2(h4.x, h4.y);
            float2 h23 = make_float2(h4.z, h4.w);
            float2 w0d = make_float2(wv.x, wv.y);
            float2 w1d = make_float2(wv.z, wv.w);
            a00 = f2fma(h01, w0d, a00);
            a01 = f2fma(h01, w1d, a01);
            a10 = f2fma(h23, w0d, a10);
            a11 = f2fma(h23, w1d, a11);
        }

        a00.x += gx00; a00.y += gx10;
        a01.x += gx01; a01.y += gx11;
        a10.x += gx20; a10.y += gx30;
        a11.x += gx21; a11.y += gx31;
        *(float2*)&P[(cl0)     * 34 + b0]     = a00;
        *(float2*)&P[(cl0 + 1) * 34 + b0]     = a01;
        *(float2*)&P[(cl0)     * 34 + b0 + 2] = a10;
        *(float2*)&P[(cl0 + 1) * 34 + b0 + 2] = a11;
        __syncthreads();

        // pointwise (2 items per thread), cell state in registers
        const int tout = dir ? (SEQT - 1 - t) : t;
        float* hTdst = (t & 1) ? (float*)&g_hT[0][dir][0][0]
                               : (float*)&g_hT[1][dir][0][0];
        {
            float iv = sigf(P[(pu)      * 34 + pb]);
            float fv = sigf(P[(8 + pu)  * 34 + pb]);
            float gv = tanhx(P[(16 + pu) * 34 + pb]);
            float ov = sigf(P[(24 + pu) * 34 + pb]);
            creg0 = fv * creg0 + iv * gv;
            float hnew = ov * tanhx(creg0);
            hTdst[(j0 + pu) * BATCH + pb] = hnew;
            out[((size_t)pb * SEQT + tout) * (2 * HID) + dir * HID + j0 + pu] = hnew;
            if (t == SEQT - 1) {
                out[OUT_HN + ((size_t)dir * BATCH + pb) * HID + j0 + pu] = hnew;
                out[OUT_CN + ((size_t)dir * BATCH + pb) * HID + j0 + pu] = creg0;
            }
        }
        {
            const int pu2 = pu + 4;
            float iv = sigf(P[(pu2)      * 34 + pb]);
            float fv = sigf(P[(8 + pu2)  * 34 + pb]);
            float gv = tanhx(P[(16 + pu2) * 34 + pb]);
            float ov = sigf(P[(24 + pu2) * 34 + pb]);
            creg1 = fv * creg1 + iv * gv;
            float hnew = ov * tanhx(creg1);
            hTdst[(j0 + pu2) * BATCH + pb] = hnew;
            out[((size_t)pb * SEQT + tout) * (2 * HID) + dir * HID + j0 + pu2] = hnew;
            if (t == SEQT - 1) {
                out[OUT_HN + ((size_t)dir * BATCH + pb) * HID + j0 + pu2] = hnew;
                out[OUT_CN + ((size_t)dir * BATCH + pb) * HID + j0 + pu2] = creg1;
            }
        }
        __syncthreads();   // all writes done before releasing arrival

        if (tid == 0) {
            int dummy;
            asm volatile("atom.release.gpu.add.s32 %0, [%1], 1;"
                         : "=r"(dummy) : "l"(arrive));
        }
    }
}

// ---------------------------------------------------------------------------
// Launch
// ---------------------------------------------------------------------------
extern "C" void kernel_launch(void* const* d_in, const int* in_sizes, int n_in,
                              void* d_out, int out_size) {
    const float* x      = (const float*)d_in[0];
    const float* h0     = (const float*)d_in[1];
    const float* c0     = (const float*)d_in[2];
    const float* w_ih_f = (const float*)d_in[3];
    const float* w_hh_f = (const float*)d_in[4];
    const float* b_ih_f = (const float*)d_in[5];
    const float* b_hh_f = (const float*)d_in[6];
    const float* w_ih_r = (const float*)d_in[7];
    const float* w_hh_r = (const float*)d_in[8];
    const float* b_ih_r = (const float*)d_in[9];
    const float* b_hh_r = (const float*)d_in[10];
    float* out = (float*)d_out;

    cudaFuncSetAttribute(lstm_persistent_kernel,
                         cudaFuncAttributeMaxDynamicSharedMemorySize, SMEM_TOTAL);

    init_state_kernel<<<128, 256>>>(h0);

    dim3 ggrid(G4 / BN, (SEQT * BATCH) / BM, 2);
    gemm_ih_kernel<<<ggrid, 256>>>(x, w_ih_f, w_ih_r,
                                   b_ih_f, b_hh_f, b_ih_r, b_hh_r);

    lstm_persistent_kernel<<<2 * NBLK_PER_DIR, 128, SMEM_TOTAL>>>(
        w_hh_f, w_hh_r, c0, out);
}